// round 2
// baseline (speedup 1.0000x reference)
#include <cuda_runtime.h>
#include <cuda_bf16.h>
#include <math_constants.h>

// ---------------- problem constants ----------------
#define B_MOL 128
#define NA 48
#define NB 96
#define HID 200
#define AFD 39
#define BFD 50        // ATOM_FDIM + BOND_FDIM
#define LPROT 1000
#define C0 50
#define C1 96
#define C2 128
#define C3 200

// ---------------- device scratch (no allocations allowed) ----------------
__device__ float g_bufA[B_MOL * 200 * LPROT];
__device__ float g_bufB[B_MOL * 200 * LPROT];
__device__ float g_emb[B_MOL * HID];
__device__ float g_prot[B_MOL * C3];

// =====================================================================
// MPNN: one block per molecule, 512 threads.
// smem: binput | msg | tmp (each 96*200 f32) = 230400 B
// =====================================================================
__global__ __launch_bounds__(512)
void mpnn_kernel(const float* __restrict__ fatoms,
                 const float* __restrict__ fbonds,
                 const int*   __restrict__ agraph,
                 const int*   __restrict__ bgraph,
                 const float* __restrict__ W_i,
                 const float* __restrict__ W_h,
                 const float* __restrict__ W_o_w,
                 const float* __restrict__ W_o_b)
{
    extern __shared__ float sm[];
    float* binput = sm;               // 19200
    float* msg    = sm + 19200;       // 19200
    float* tmp    = sm + 38400;       // 19200

    const int b   = blockIdx.x;
    const int tid = threadIdx.x;
    const float* fb = fbonds + (size_t)b * NB * BFD;
    const float* fa = fatoms + (size_t)b * NA * AFD;
    const int*   bg = bgraph + (size_t)b * NB * 6;
    const int*   ag = agraph + (size_t)b * NA * 6;

    // stage fbonds into smem (tmp)
    for (int idx = tid; idx < NB * BFD; idx += 512) tmp[idx] = fb[idx];
    __syncthreads();

    // binput = fb @ W_i ; msg = relu(binput). 4x4 register tile, float4 weights.
    // tasks: 24 row-groups x 50 col-groups
    for (int task = tid; task < 24 * 50; task += 512) {
        const int i0 = (task / 50) * 4;
        const int h0 = (task % 50) * 4;
        float a[4][4];
        #pragma unroll
        for (int r = 0; r < 4; r++)
            #pragma unroll
            for (int c = 0; c < 4; c++) a[r][c] = 0.f;
        for (int k = 0; k < BFD; k++) {
            float4 w = *(const float4*)(W_i + k * HID + h0);
            #pragma unroll
            for (int r = 0; r < 4; r++) {
                float x = tmp[(i0 + r) * BFD + k];
                a[r][0] = fmaf(x, w.x, a[r][0]);
                a[r][1] = fmaf(x, w.y, a[r][1]);
                a[r][2] = fmaf(x, w.z, a[r][2]);
                a[r][3] = fmaf(x, w.w, a[r][3]);
            }
        }
        #pragma unroll
        for (int r = 0; r < 4; r++)
            #pragma unroll
            for (int c = 0; c < 4; c++) {
                binput[(i0 + r) * HID + h0 + c] = a[r][c];
                msg[(i0 + r) * HID + h0 + c]    = fmaxf(a[r][c], 0.f);
            }
    }
    __syncthreads();

    // DEPTH-1 = 2 message passing iterations
    for (int d = 0; d < 2; d++) {
        // tmp = gather-sum of msg rows
        for (int idx = tid; idx < NB * HID; idx += 512) {
            int i = idx / HID, h = idx - i * HID;
            float s = 0.f;
            #pragma unroll
            for (int j = 0; j < 6; j++) s += msg[bg[i * 6 + j] * HID + h];
            tmp[idx] = s;
        }
        __syncthreads();
        // msg = relu(binput + tmp @ W_h)
        for (int task = tid; task < 24 * 50; task += 512) {
            const int i0 = (task / 50) * 4;
            const int h0 = (task % 50) * 4;
            float a[4][4];
            #pragma unroll
            for (int r = 0; r < 4; r++)
                #pragma unroll
                for (int c = 0; c < 4; c++) a[r][c] = binput[(i0 + r) * HID + h0 + c];
            for (int k = 0; k < HID; k++) {
                float4 w = *(const float4*)(W_h + k * HID + h0);
                #pragma unroll
                for (int r = 0; r < 4; r++) {
                    float x = tmp[(i0 + r) * HID + k];
                    a[r][0] = fmaf(x, w.x, a[r][0]);
                    a[r][1] = fmaf(x, w.y, a[r][1]);
                    a[r][2] = fmaf(x, w.z, a[r][2]);
                    a[r][3] = fmaf(x, w.w, a[r][3]);
                }
            }
            #pragma unroll
            for (int r = 0; r < 4; r++)
                #pragma unroll
                for (int c = 0; c < 4; c++)
                    msg[(i0 + r) * HID + h0 + c] = fmaxf(a[r][c], 0.f);
        }
        __syncthreads();
    }

    // anei (48x200) into tmp[0:9600]; stage fatoms into tmp[9600:...]
    for (int idx = tid; idx < NA * HID; idx += 512) {
        int a = idx / HID, h = idx - a * HID;
        float s = 0.f;
        #pragma unroll
        for (int j = 0; j < 6; j++) s += msg[ag[a * 6 + j] * HID + h];
        tmp[idx] = s;
    }
    for (int idx = tid; idx < NA * AFD; idx += 512) tmp[NA * HID + idx] = fa[idx];
    __syncthreads();

    // atom_h = relu([fa, anei] @ W_o + b) into binput rows 0..47
    for (int task = tid; task < 12 * 50; task += 512) {
        const int a0i = (task / 50) * 4;
        const int h0  = (task % 50) * 4;
        float4 bb = *(const float4*)(W_o_b + h0);
        float a[4][4];
        #pragma unroll
        for (int r = 0; r < 4; r++) { a[r][0]=bb.x; a[r][1]=bb.y; a[r][2]=bb.z; a[r][3]=bb.w; }
        const float* fas = tmp + NA * HID;
        for (int k = 0; k < AFD; k++) {
            float4 w = *(const float4*)(W_o_w + k * HID + h0);
            #pragma unroll
            for (int r = 0; r < 4; r++) {
                float x = fas[(a0i + r) * AFD + k];
                a[r][0] = fmaf(x, w.x, a[r][0]);
                a[r][1] = fmaf(x, w.y, a[r][1]);
                a[r][2] = fmaf(x, w.z, a[r][2]);
                a[r][3] = fmaf(x, w.w, a[r][3]);
            }
        }
        for (int k = 0; k < HID; k++) {
            float4 w = *(const float4*)(W_o_w + (AFD + k) * HID + h0);
            #pragma unroll
            for (int r = 0; r < 4; r++) {
                float x = tmp[(a0i + r) * HID + k];
                a[r][0] = fmaf(x, w.x, a[r][0]);
                a[r][1] = fmaf(x, w.y, a[r][1]);
                a[r][2] = fmaf(x, w.z, a[r][2]);
                a[r][3] = fmaf(x, w.w, a[r][3]);
            }
        }
        #pragma unroll
        for (int r = 0; r < 4; r++)
            #pragma unroll
            for (int c = 0; c < 4; c++)
                binput[(a0i + r) * HID + h0 + c] = fmaxf(a[r][c], 0.f);
    }
    __syncthreads();

    // deterministic mean over atoms
    for (int h = tid; h < HID; h += 512) {
        float s = 0.f;
        for (int a = 0; a < NA; a++) s += binput[a * HID + h];
        g_emb[b * HID + h] = s * (1.f / (float)NA);
    }
}

// =====================================================================
// protein embedding gather -> (B, 50, L) channel-major
// =====================================================================
__global__ void embed_kernel(const int* __restrict__ seq,
                             const float* __restrict__ E)
{
    int idx = blockIdx.x * blockDim.x + threadIdx.x;
    const int total = B_MOL * C0 * LPROT;
    if (idx >= total) return;
    int l = idx % LPROT;
    int c = (idx / LPROT) % C0;
    int b = idx / (LPROT * C0);
    g_bufA[idx] = E[seq[b * LPROT + l] * C0 + c];
}

// =====================================================================
// 1D conv + bias + relu, "same" padding, channel-major.
// Block 256 thr: tile = 64 out-channels x 64 positions.
// Thread: 1 oc x 16 positions; per Cin iter: ~6 LDS.128 + K LDG vs 16*K FMA.
// =====================================================================
template <int K, int CIN>
__global__ __launch_bounds__(256, 3)
void conv_relu_kernel(const float* __restrict__ in,
                      const float* __restrict__ w,
                      const float* __restrict__ bias,
                      float* __restrict__ out,
                      int Cout)
{
    __shared__ float s_in[CIN * 80];
    constexpr int NQ = (16 + K - 1 + 3) / 4;   // float4 loads per cin (5 or 6)

    const int b  = blockIdx.x;
    const int l0 = blockIdx.y * 64;
    const int o0 = blockIdx.z * 64;
    const int tid = threadIdx.x;

    // stage input tile: CIN rows x 80 floats (64 + K - 1 used, rest zero)
    const float* inb = in + (size_t)b * CIN * LPROT;
    for (int idx = tid; idx < CIN * 80; idx += 256) {
        int ci = idx / 80, t = idx - ci * 80;
        int gl = l0 + t - K / 2;
        float v = 0.f;
        if (t < 64 + K - 1 && gl >= 0 && gl < LPROT) v = inb[ci * LPROT + gl];
        s_in[idx] = v;
    }
    __syncthreads();

    const int oc_l = tid >> 2;        // 0..63
    const int pg   = tid & 3;         // position group: 16 positions each
    const int oc   = o0 + oc_l;
    const bool valid = (oc < Cout);
    const float* wrow = w + (size_t)(valid ? oc : 0) * CIN * K;

    float acc[16];
    #pragma unroll
    for (int r = 0; r < 16; r++) acc[r] = 0.f;

    for (int ci = 0; ci < CIN; ci++) {
        float rin[NQ * 4];
        const float4* sp = (const float4*)(s_in + ci * 80 + pg * 16);
        #pragma unroll
        for (int q = 0; q < NQ; q++) {
            float4 v = sp[q];
            rin[q * 4 + 0] = v.x; rin[q * 4 + 1] = v.y;
            rin[q * 4 + 2] = v.z; rin[q * 4 + 3] = v.w;
        }
        float wv[K];
        #pragma unroll
        for (int t = 0; t < K; t++) wv[t] = __ldg(wrow + ci * K + t);
        #pragma unroll
        for (int t = 0; t < K; t++)
            #pragma unroll
            for (int r = 0; r < 16; r++)
                acc[r] = fmaf(wv[t], rin[r + t], acc[r]);
    }

    if (valid) {
        const float bv = bias[oc];
        float* op = out + ((size_t)b * Cout + oc) * LPROT + l0 + pg * 16;
        const int lbase = l0 + pg * 16;
        #pragma unroll
        for (int r = 0; r < 16; r++)
            if (lbase + r < LPROT) op[r] = fmaxf(acc[r] + bv, 0.f);
    }
}

// =====================================================================
// max over L per (b, channel): one warp per row
// =====================================================================
__global__ void maxpool_kernel(const float* __restrict__ in, float* __restrict__ out)
{
    int gwarp = (blockIdx.x * blockDim.x + threadIdx.x) >> 5;
    int lane  = threadIdx.x & 31;
    const int rows = B_MOL * C3;
    if (gwarp >= rows) return;
    const float* p = in + (size_t)gwarp * LPROT;
    float m = -CUDART_INF_F;
    for (int l = lane; l < LPROT; l += 32) m = fmaxf(m, p[l]);
    #pragma unroll
    for (int s = 16; s; s >>= 1) m = fmaxf(m, __shfl_xor_sync(0xFFFFFFFFu, m, s));
    if (lane == 0) out[gwarp] = m;
}

// =====================================================================
// FC head: one block per batch row. 400 -> 200 -> 100 -> 1
// =====================================================================
__global__ void fc_kernel(const float* __restrict__ emb,
                          const float* __restrict__ prot,
                          const float* __restrict__ w0, const float* __restrict__ b0,
                          const float* __restrict__ w1, const float* __restrict__ b1,
                          const float* __restrict__ w2, const float* __restrict__ b2,
                          float* __restrict__ out)
{
    __shared__ float x[400];
    __shared__ float h1[200];
    __shared__ float h2[100];
    __shared__ float red[256];
    const int b = blockIdx.x;
    const int tid = threadIdx.x;

    for (int i = tid; i < 200; i += 256) {
        x[i]       = emb[b * 200 + i];
        x[200 + i] = prot[b * 200 + i];
    }
    __syncthreads();
    for (int j = tid; j < 200; j += 256) {
        float s = b0[j];
        for (int k = 0; k < 400; k++) s = fmaf(x[k], w0[k * 200 + j], s);
        h1[j] = fmaxf(s, 0.f);
    }
    __syncthreads();
    for (int j = tid; j < 100; j += 256) {
        float s = b1[j];
        for (int k = 0; k < 200; k++) s = fmaf(h1[k], w1[k * 100 + j], s);
        h2[j] = fmaxf(s, 0.f);
    }
    __syncthreads();
    float s = 0.f;
    for (int k = tid; k < 100; k += 256) s = fmaf(h2[k], w2[k], s);
    red[tid] = s;
    __syncthreads();
    for (int st = 128; st; st >>= 1) {
        if (tid < st) red[tid] += red[tid + st];
        __syncthreads();
    }
    if (tid == 0) out[b] = red[0] + b2[0];
}

// =====================================================================
extern "C" void kernel_launch(void* const* d_in, const int* in_sizes, int n_in,
                              void* d_out, int out_size)
{
    const float* fatoms  = (const float*)d_in[0];
    const float* fbonds  = (const float*)d_in[1];
    const int*   agraph  = (const int*)  d_in[2];
    const int*   bgraph  = (const int*)  d_in[3];
    const int*   seq     = (const int*)  d_in[4];
    const float* W_i     = (const float*)d_in[5];
    const float* W_h     = (const float*)d_in[6];
    const float* W_o_w   = (const float*)d_in[7];
    const float* W_o_b   = (const float*)d_in[8];
    const float* embedP  = (const float*)d_in[9];
    const float* c0w     = (const float*)d_in[10];
    const float* c0b     = (const float*)d_in[11];
    const float* c1w     = (const float*)d_in[12];
    const float* c1b     = (const float*)d_in[13];
    const float* c2w     = (const float*)d_in[14];
    const float* c2b     = (const float*)d_in[15];
    const float* fc0w    = (const float*)d_in[16];
    const float* fc0b    = (const float*)d_in[17];
    const float* fc1w    = (const float*)d_in[18];
    const float* fc1b    = (const float*)d_in[19];
    const float* fc2w    = (const float*)d_in[20];
    const float* fc2b    = (const float*)d_in[21];
    float* out = (float*)d_out;

    float *bufA, *bufB, *emb, *prot;
    cudaGetSymbolAddress((void**)&bufA, g_bufA);
    cudaGetSymbolAddress((void**)&bufB, g_bufB);
    cudaGetSymbolAddress((void**)&emb,  g_emb);
    cudaGetSymbolAddress((void**)&prot, g_prot);

    const int mpnn_smem = 3 * NB * HID * sizeof(float);   // 230400 B
    cudaFuncSetAttribute(mpnn_kernel, cudaFuncAttributeMaxDynamicSharedMemorySize, mpnn_smem);

    // 1. MPNN -> g_emb
    mpnn_kernel<<<B_MOL, 512, mpnn_smem>>>(fatoms, fbonds, agraph, bgraph,
                                           W_i, W_h, W_o_w, W_o_b);

    // 2. protein embedding -> bufA (B,50,L)
    {
        int total = B_MOL * C0 * LPROT;
        embed_kernel<<<(total + 255) / 256, 256>>>(seq, embedP);
    }

    // 3. conv tower
    {
        dim3 g(B_MOL, (LPROT + 63) / 64, (C1 + 63) / 64);
        conv_relu_kernel<3, C0><<<g, 256>>>(bufA, c0w, c0b, bufB, C1);
    }
    {
        dim3 g(B_MOL, (LPROT + 63) / 64, (C2 + 63) / 64);
        conv_relu_kernel<5, C1><<<g, 256>>>(bufB, c1w, c1b, bufA, C2);
    }
    {
        dim3 g(B_MOL, (LPROT + 63) / 64, (C3 + 63) / 64);
        conv_relu_kernel<7, C2><<<g, 256>>>(bufA, c2w, c2b, bufB, C3);
    }

    // 4. adaptive max pool -> g_prot
    {
        int rows = B_MOL * C3;
        int blocks = (rows + 7) / 8;
        maxpool_kernel<<<blocks, 256>>>(bufB, prot);
    }

    // 5. FC head -> out
    fc_kernel<<<B_MOL, 256>>>(emb, prot, fc0w, fc0b, fc1w, fc1b, fc2w, fc2b, out);
}

// round 3
// speedup vs baseline: 1.8193x; 1.8193x over previous
#include <cuda_runtime.h>
#include <cuda_bf16.h>
#include <math_constants.h>

// ---------------- problem constants ----------------
#define B_MOL 128
#define NA 48
#define NB 96
#define HID 200
#define AFD 39
#define BFD 50        // ATOM_FDIM + BOND_FDIM
#define LPROT 1000
#define C0 50
#define C1 96
#define C2 128
#define C3 200

// ---------------- device scratch (no allocations allowed) ----------------
__device__ float g_bufA[B_MOL * 200 * LPROT];
__device__ float g_bufB[B_MOL * 200 * LPROT];
__device__ float g_emb[B_MOL * HID];
__device__ float g_prot[B_MOL * C3];
__device__ float g_wt[256 * 128 * 7];      // transposed weights, reused per layer

// =====================================================================
// MPNN: one block per molecule, 512 threads.
// smem: binput | msg | tmp (each 96*200 f32) = 230400 B
// =====================================================================
__global__ __launch_bounds__(512)
void mpnn_kernel(const float* __restrict__ fatoms,
                 const float* __restrict__ fbonds,
                 const int*   __restrict__ agraph,
                 const int*   __restrict__ bgraph,
                 const float* __restrict__ W_i,
                 const float* __restrict__ W_h,
                 const float* __restrict__ W_o_w,
                 const float* __restrict__ W_o_b)
{
    extern __shared__ float sm[];
    float* binput = sm;               // 19200
    float* msg    = sm + 19200;       // 19200
    float* tmp    = sm + 38400;       // 19200

    const int b   = blockIdx.x;
    const int tid = threadIdx.x;
    const float* fb = fbonds + (size_t)b * NB * BFD;
    const float* fa = fatoms + (size_t)b * NA * AFD;
    const int*   bg = bgraph + (size_t)b * NB * 6;
    const int*   ag = agraph + (size_t)b * NA * 6;

    for (int idx = tid; idx < NB * BFD; idx += 512) tmp[idx] = fb[idx];
    __syncthreads();

    // binput = fb @ W_i ; msg = relu(binput). 4x4 register tile, float4 weights.
    for (int task = tid; task < 24 * 50; task += 512) {
        const int i0 = (task / 50) * 4;
        const int h0 = (task % 50) * 4;
        float a[4][4];
        #pragma unroll
        for (int r = 0; r < 4; r++)
            #pragma unroll
            for (int c = 0; c < 4; c++) a[r][c] = 0.f;
        for (int k = 0; k < BFD; k++) {
            float4 w = *(const float4*)(W_i + k * HID + h0);
            #pragma unroll
            for (int r = 0; r < 4; r++) {
                float x = tmp[(i0 + r) * BFD + k];
                a[r][0] = fmaf(x, w.x, a[r][0]);
                a[r][1] = fmaf(x, w.y, a[r][1]);
                a[r][2] = fmaf(x, w.z, a[r][2]);
                a[r][3] = fmaf(x, w.w, a[r][3]);
            }
        }
        #pragma unroll
        for (int r = 0; r < 4; r++)
            #pragma unroll
            for (int c = 0; c < 4; c++) {
                binput[(i0 + r) * HID + h0 + c] = a[r][c];
                msg[(i0 + r) * HID + h0 + c]    = fmaxf(a[r][c], 0.f);
            }
    }
    __syncthreads();

    for (int d = 0; d < 2; d++) {
        for (int idx = tid; idx < NB * HID; idx += 512) {
            int i = idx / HID, h = idx - i * HID;
            float s = 0.f;
            #pragma unroll
            for (int j = 0; j < 6; j++) s += msg[bg[i * 6 + j] * HID + h];
            tmp[idx] = s;
        }
        __syncthreads();
        for (int task = tid; task < 24 * 50; task += 512) {
            const int i0 = (task / 50) * 4;
            const int h0 = (task % 50) * 4;
            float a[4][4];
            #pragma unroll
            for (int r = 0; r < 4; r++)
                #pragma unroll
                for (int c = 0; c < 4; c++) a[r][c] = binput[(i0 + r) * HID + h0 + c];
            for (int k = 0; k < HID; k++) {
                float4 w = *(const float4*)(W_h + k * HID + h0);
                #pragma unroll
                for (int r = 0; r < 4; r++) {
                    float x = tmp[(i0 + r) * HID + k];
                    a[r][0] = fmaf(x, w.x, a[r][0]);
                    a[r][1] = fmaf(x, w.y, a[r][1]);
                    a[r][2] = fmaf(x, w.z, a[r][2]);
                    a[r][3] = fmaf(x, w.w, a[r][3]);
                }
            }
            #pragma unroll
            for (int r = 0; r < 4; r++)
                #pragma unroll
                for (int c = 0; c < 4; c++)
                    msg[(i0 + r) * HID + h0 + c] = fmaxf(a[r][c], 0.f);
        }
        __syncthreads();
    }

    for (int idx = tid; idx < NA * HID; idx += 512) {
        int a = idx / HID, h = idx - a * HID;
        float s = 0.f;
        #pragma unroll
        for (int j = 0; j < 6; j++) s += msg[ag[a * 6 + j] * HID + h];
        tmp[idx] = s;
    }
    for (int idx = tid; idx < NA * AFD; idx += 512) tmp[NA * HID + idx] = fa[idx];
    __syncthreads();

    for (int task = tid; task < 12 * 50; task += 512) {
        const int a0i = (task / 50) * 4;
        const int h0  = (task % 50) * 4;
        float4 bb = *(const float4*)(W_o_b + h0);
        float a[4][4];
        #pragma unroll
        for (int r = 0; r < 4; r++) { a[r][0]=bb.x; a[r][1]=bb.y; a[r][2]=bb.z; a[r][3]=bb.w; }
        const float* fas = tmp + NA * HID;
        for (int k = 0; k < AFD; k++) {
            float4 w = *(const float4*)(W_o_w + k * HID + h0);
            #pragma unroll
            for (int r = 0; r < 4; r++) {
                float x = fas[(a0i + r) * AFD + k];
                a[r][0] = fmaf(x, w.x, a[r][0]);
                a[r][1] = fmaf(x, w.y, a[r][1]);
                a[r][2] = fmaf(x, w.z, a[r][2]);
                a[r][3] = fmaf(x, w.w, a[r][3]);
            }
        }
        for (int k = 0; k < HID; k++) {
            float4 w = *(const float4*)(W_o_w + (AFD + k) * HID + h0);
            #pragma unroll
            for (int r = 0; r < 4; r++) {
                float x = tmp[(a0i + r) * HID + k];
                a[r][0] = fmaf(x, w.x, a[r][0]);
                a[r][1] = fmaf(x, w.y, a[r][1]);
                a[r][2] = fmaf(x, w.z, a[r][2]);
                a[r][3] = fmaf(x, w.w, a[r][3]);
            }
        }
        #pragma unroll
        for (int r = 0; r < 4; r++)
            #pragma unroll
            for (int c = 0; c < 4; c++)
                binput[(a0i + r) * HID + h0 + c] = fmaxf(a[r][c], 0.f);
    }
    __syncthreads();

    for (int h = tid; h < HID; h += 512) {
        float s = 0.f;
        for (int a = 0; a < NA; a++) s += binput[a * HID + h];
        g_emb[b * HID + h] = s * (1.f / (float)NA);
    }
}

// =====================================================================
// protein embedding gather -> (B, 50, L) channel-major
// =====================================================================
__global__ void embed_kernel(const int* __restrict__ seq,
                             const float* __restrict__ E)
{
    int idx = blockIdx.x * blockDim.x + threadIdx.x;
    const int total = B_MOL * C0 * LPROT;
    if (idx >= total) return;
    int l = idx % LPROT;
    int c = (idx / LPROT) % C0;
    int b = idx / (LPROT * C0);
    g_bufA[idx] = E[seq[b * LPROT + l] * C0 + c];
}

// =====================================================================
// weight transpose: w[oc][ci][k] -> wt[ci*K+k][oc], oc padded to OCP with 0
// =====================================================================
__global__ void wt_transpose_kernel(const float* __restrict__ w,
                                    float* __restrict__ wt,
                                    int Cin, int K, int Cout, int OCP)
{
    int idx = blockIdx.x * blockDim.x + threadIdx.x;
    int total = Cin * K * OCP;
    if (idx >= total) return;
    int oc  = idx % OCP;
    int row = idx / OCP;                 // ci*K + k
    wt[idx] = (oc < Cout) ? w[(size_t)oc * Cin * K + row] : 0.f;
}

// =====================================================================
// conv as smem-smem implicit GEMM.
// Block: 64 oc x 128 positions, 256 threads (ty=oc-group of 4, tx=pos-group of 8).
// Cin chunked by 16; all inner operands from shared memory.
// =====================================================================
template <int K>
__global__ __launch_bounds__(256)
void conv_gemm_kernel(const float* __restrict__ in,
                      const float* __restrict__ wt,    // [Cin*K][OCP]
                      const float* __restrict__ bias,
                      float* __restrict__ out,
                      int Cin, int Cout, int OCP)
{
    __shared__ float s_in[16][136];
    __shared__ float s_w[16 * K][64];

    const int b  = blockIdx.x;
    const int l0 = blockIdx.y * 128;
    const int o0 = blockIdx.z * 64;
    const int tid = threadIdx.x;
    const int ty = tid >> 4;      // 0..15 -> oc = o0 + ty*4 .. +3
    const int tx = tid & 15;      // 0..15 -> pos = l0 + tx*8 .. +7

    float acc[4][8];
    #pragma unroll
    for (int a = 0; a < 4; a++)
        #pragma unroll
        for (int r = 0; r < 8; r++) acc[a][r] = 0.f;

    const float* inb = in + (size_t)b * Cin * LPROT;
    const int nchunk = (Cin + 15) / 16;

    for (int c = 0; c < nchunk; c++) {
        // stage input tile (16 x 136)
        for (int idx = tid; idx < 16 * 136; idx += 256) {
            int ci = idx / 136, t = idx - ci * 136;
            int cig = c * 16 + ci;
            int gl = l0 + t - K / 2;
            float v = 0.f;
            if (cig < Cin && t < 128 + K - 1 && gl >= 0 && gl < LPROT)
                v = inb[cig * LPROT + gl];
            s_in[ci][t] = v;
        }
        // stage weight tile (16K x 64), contiguous rows of wt
        for (int idx = tid; idx < 16 * K * 64; idx += 256) {
            int row = idx >> 6, oc = idx & 63;
            int cig = c * 16 + row / K;
            float v = 0.f;
            if (cig < Cin)
                v = wt[(size_t)(cig * K + (row - (row / K) * K)) * OCP + o0 + oc];
            s_w[row][oc] = v;
        }
        __syncthreads();

        #pragma unroll 2
        for (int ci = 0; ci < 16; ci++) {
            float rin[16];
            const float4* sp = (const float4*)&s_in[ci][tx * 8];
            #pragma unroll
            for (int q = 0; q < 4; q++) {
                float4 v = sp[q];
                rin[q * 4 + 0] = v.x; rin[q * 4 + 1] = v.y;
                rin[q * 4 + 2] = v.z; rin[q * 4 + 3] = v.w;
            }
            #pragma unroll
            for (int k = 0; k < K; k++) {
                float4 w = *(const float4*)&s_w[ci * K + k][ty * 4];
                #pragma unroll
                for (int r = 0; r < 8; r++) {
                    float x = rin[r + k];
                    acc[0][r] = fmaf(w.x, x, acc[0][r]);
                    acc[1][r] = fmaf(w.y, x, acc[1][r]);
                    acc[2][r] = fmaf(w.z, x, acc[2][r]);
                    acc[3][r] = fmaf(w.w, x, acc[3][r]);
                }
            }
        }
        __syncthreads();
    }

    #pragma unroll
    for (int a = 0; a < 4; a++) {
        int oc = o0 + ty * 4 + a;
        if (oc >= Cout) continue;
        float bv = bias[oc];
        float* op = out + ((size_t)b * Cout + oc) * LPROT;
        #pragma unroll
        for (int r = 0; r < 8; r++) {
            int l = l0 + tx * 8 + r;
            if (l < LPROT) op[l] = fmaxf(acc[a][r] + bv, 0.f);
        }
    }
}

// =====================================================================
// max over L per (b, channel): one warp per row
// =====================================================================
__global__ void maxpool_kernel(const float* __restrict__ in, float* __restrict__ out)
{
    int gwarp = (blockIdx.x * blockDim.x + threadIdx.x) >> 5;
    int lane  = threadIdx.x & 31;
    const int rows = B_MOL * C3;
    if (gwarp >= rows) return;
    const float* p = in + (size_t)gwarp * LPROT;
    float m = -CUDART_INF_F;
    for (int l = lane; l < LPROT; l += 32) m = fmaxf(m, p[l]);
    #pragma unroll
    for (int s = 16; s; s >>= 1) m = fmaxf(m, __shfl_xor_sync(0xFFFFFFFFu, m, s));
    if (lane == 0) out[gwarp] = m;
}

// =====================================================================
// FC head: one block per batch row. 400 -> 200 -> 100 -> 1
// =====================================================================
__global__ void fc_kernel(const float* __restrict__ emb,
                          const float* __restrict__ prot,
                          const float* __restrict__ w0, const float* __restrict__ b0,
                          const float* __restrict__ w1, const float* __restrict__ b1,
                          const float* __restrict__ w2, const float* __restrict__ b2,
                          float* __restrict__ out)
{
    __shared__ float x[400];
    __shared__ float h1[200];
    __shared__ float h2[100];
    __shared__ float red[256];
    const int b = blockIdx.x;
    const int tid = threadIdx.x;

    for (int i = tid; i < 200; i += 256) {
        x[i]       = emb[b * 200 + i];
        x[200 + i] = prot[b * 200 + i];
    }
    __syncthreads();
    for (int j = tid; j < 200; j += 256) {
        float s = b0[j];
        for (int k = 0; k < 400; k++) s = fmaf(x[k], w0[k * 200 + j], s);
        h1[j] = fmaxf(s, 0.f);
    }
    __syncthreads();
    for (int j = tid; j < 100; j += 256) {
        float s = b1[j];
        for (int k = 0; k < 200; k++) s = fmaf(h1[k], w1[k * 100 + j], s);
        h2[j] = fmaxf(s, 0.f);
    }
    __syncthreads();
    float s = 0.f;
    for (int k = tid; k < 100; k += 256) s = fmaf(h2[k], w2[k], s);
    red[tid] = s;
    __syncthreads();
    for (int st = 128; st; st >>= 1) {
        if (tid < st) red[tid] += red[tid + st];
        __syncthreads();
    }
    if (tid == 0) out[b] = red[0] + b2[0];
}

// =====================================================================
extern "C" void kernel_launch(void* const* d_in, const int* in_sizes, int n_in,
                              void* d_out, int out_size)
{
    const float* fatoms  = (const float*)d_in[0];
    const float* fbonds  = (const float*)d_in[1];
    const int*   agraph  = (const int*)  d_in[2];
    const int*   bgraph  = (const int*)  d_in[3];
    const int*   seq     = (const int*)  d_in[4];
    const float* W_i     = (const float*)d_in[5];
    const float* W_h     = (const float*)d_in[6];
    const float* W_o_w   = (const float*)d_in[7];
    const float* W_o_b   = (const float*)d_in[8];
    const float* embedP  = (const float*)d_in[9];
    const float* c0w     = (const float*)d_in[10];
    const float* c0b     = (const float*)d_in[11];
    const float* c1w     = (const float*)d_in[12];
    const float* c1b     = (const float*)d_in[13];
    const float* c2w     = (const float*)d_in[14];
    const float* c2b     = (const float*)d_in[15];
    const float* fc0w    = (const float*)d_in[16];
    const float* fc0b    = (const float*)d_in[17];
    const float* fc1w    = (const float*)d_in[18];
    const float* fc1b    = (const float*)d_in[19];
    const float* fc2w    = (const float*)d_in[20];
    const float* fc2b    = (const float*)d_in[21];
    float* out = (float*)d_out;

    float *bufA, *bufB, *emb, *prot, *wt;
    cudaGetSymbolAddress((void**)&bufA, g_bufA);
    cudaGetSymbolAddress((void**)&bufB, g_bufB);
    cudaGetSymbolAddress((void**)&emb,  g_emb);
    cudaGetSymbolAddress((void**)&prot, g_prot);
    cudaGetSymbolAddress((void**)&wt,   g_wt);

    const int mpnn_smem = 3 * NB * HID * sizeof(float);   // 230400 B
    cudaFuncSetAttribute(mpnn_kernel, cudaFuncAttributeMaxDynamicSharedMemorySize, mpnn_smem);

    // 1. MPNN -> g_emb
    mpnn_kernel<<<B_MOL, 512, mpnn_smem>>>(fatoms, fbonds, agraph, bgraph,
                                           W_i, W_h, W_o_w, W_o_b);

    // 2. protein embedding -> bufA (B,50,L)
    {
        int total = B_MOL * C0 * LPROT;
        embed_kernel<<<(total + 255) / 256, 256>>>(seq, embedP);
    }

    // 3. conv tower (transpose weights, then implicit GEMM) — stream order
    //    serializes reuse of the single g_wt buffer.
    {   // conv0: Cin=50, Cout=96, K=3, OCP=128
        int total = C0 * 3 * 128;
        wt_transpose_kernel<<<(total + 255) / 256, 256>>>(c0w, wt, C0, 3, C1, 128);
        dim3 g(B_MOL, (LPROT + 127) / 128, (C1 + 63) / 64);
        conv_gemm_kernel<3><<<g, 256>>>(bufA, wt, c0b, bufB, C0, C1, 128);
    }
    {   // conv1: Cin=96, Cout=128, K=5, OCP=128
        int total = C1 * 5 * 128;
        wt_transpose_kernel<<<(total + 255) / 256, 256>>>(c1w, wt, C1, 5, C2, 128);
        dim3 g(B_MOL, (LPROT + 127) / 128, (C2 + 63) / 64);
        conv_gemm_kernel<5><<<g, 256>>>(bufB, wt, c1b, bufA, C1, C2, 128);
    }
    {   // conv2: Cin=128, Cout=200, K=7, OCP=256
        int total = C2 * 7 * 256;
        wt_transpose_kernel<<<(total + 255) / 256, 256>>>(c2w, wt, C2, 7, C3, 256);
        dim3 g(B_MOL, (LPROT + 127) / 128, (C3 + 63) / 64);
        conv_gemm_kernel<7><<<g, 256>>>(bufA, wt, c2b, bufB, C2, C3, 256);
    }

    // 4. adaptive max pool -> g_prot
    {
        int rows = B_MOL * C3;
        int blocks = (rows + 7) / 8;
        maxpool_kernel<<<blocks, 256>>>(bufB, prot);
    }

    // 5. FC head -> out
    fc_kernel<<<B_MOL, 256>>>(emb, prot, fc0w, fc0b, fc1w, fc1b, fc2w, fc2b, out);
}